// round 10
// baseline (speedup 1.0000x reference)
#include <cuda_runtime.h>
#include <cuda_bf16.h>
#include <cuda_fp16.h>
#include <math.h>
#include <cstdint>

#define T_TOK 8192
#define EMB   1024
#define DFF   4096
#define NH    16
#define DH    64
#define SEQ   2048
#define NBATCH 4
#define QKVS  3072

// ================= PTX helpers =================
__device__ __forceinline__ uint32_t smem_u32(const void* p) {
    uint32_t a;
    asm("{ .reg .u64 t; cvta.to.shared.u64 t, %1; cvt.u32.u64 %0, t; }" : "=r"(a) : "l"(p));
    return a;
}
#define CP_ASYNC16(dst, src) \
    asm volatile("cp.async.cg.shared.global [%0], [%1], 16;" :: "r"(dst), "l"(src))
#define CP_COMMIT() asm volatile("cp.async.commit_group;" ::: "memory")
#define CP_WAIT1()  asm volatile("cp.async.wait_group 1;" ::: "memory")
#define CP_WAIT0()  asm volatile("cp.async.wait_group 0;" ::: "memory")

__device__ __forceinline__ void ldsm4(uint32_t* r, uint32_t addr) {
    asm volatile("ldmatrix.sync.aligned.m8n8.x4.shared.b16 {%0,%1,%2,%3}, [%4];"
                 : "=r"(r[0]), "=r"(r[1]), "=r"(r[2]), "=r"(r[3]) : "r"(addr));
}
__device__ __forceinline__ void ldsm4t(uint32_t* r, uint32_t addr) {
    asm volatile("ldmatrix.sync.aligned.m8n8.x4.trans.shared.b16 {%0,%1,%2,%3}, [%4];"
                 : "=r"(r[0]), "=r"(r[1]), "=r"(r[2]), "=r"(r[3]) : "r"(addr));
}
__device__ __forceinline__ void mma_f16(float* c, const uint32_t* a, const uint32_t* b) {
    asm volatile(
        "mma.sync.aligned.m16n8k16.row.col.f32.f16.f16.f32 "
        "{%0,%1,%2,%3}, {%4,%5,%6,%7}, {%8,%9}, {%0,%1,%2,%3};"
        : "+f"(c[0]), "+f"(c[1]), "+f"(c[2]), "+f"(c[3])
        : "r"(a[0]), "r"(a[1]), "r"(a[2]), "r"(a[3]), "r"(b[0]), "r"(b[1]));
}
__device__ __forceinline__ float ex2(float x) {
    float y;
    asm("ex2.approx.f32 %0, %1;" : "=f"(y) : "f"(x));
    return y;
}
__device__ __forceinline__ uint32_t pack2h(float a, float b) {
    __half2 h = __floats2half2_rn(a, b);
    return *(uint32_t*)&h;
}

// ================= scratch =================
__device__ __half g_xn[(size_t)T_TOK * EMB];
__device__ __half g_qkvh[(size_t)T_TOK * QKVS];
__device__ float g_x1[(size_t)T_TOK * EMB];
__device__ __half g_at[(size_t)T_TOK * EMB];
__device__ __half g_h [(size_t)T_TOK * DFF];
__device__ __half g_wqkv[(size_t)3 * EMB * EMB];
__device__ __half g_wo[(size_t)EMB * EMB];
__device__ __half g_w1[(size_t)DFF * EMB];
__device__ __half g_w2[(size_t)EMB * DFF];

// ================= fused weight fp32 -> fp16 =================
struct CvtJobs {
    const float* src[6];
    __half*      dst[6];
    int          n4[6];
    float        scale[6];
};
__global__ void cvt_all_kernel(CvtJobs jobs) {
    int j = blockIdx.y;
    int i = blockIdx.x * blockDim.x + threadIdx.x;
    if (i >= jobs.n4[j]) return;
    float sc = jobs.scale[j];
    float4 v = ((const float4*)jobs.src[j])[i];
    ((uint32_t*)jobs.dst[j])[i * 2 + 0] = pack2h(v.x * sc, v.y * sc);
    ((uint32_t*)jobs.dst[j])[i * 2 + 1] = pack2h(v.z * sc, v.w * sc);
}

// ================= LayerNorm -> fp16 =================
__global__ void layernorm_kernel(const float* __restrict__ x,
                                 const float* __restrict__ gamma,
                                 const float* __restrict__ beta,
                                 __half* __restrict__ o) {
    int row = blockIdx.x;
    int t = threadIdx.x;
    const float4* xr = (const float4*)(x + (size_t)row * EMB);
    float4 v = xr[t];
    float s  = v.x + v.y + v.z + v.w;
    float ss = v.x * v.x + v.y * v.y + v.z * v.z + v.w * v.w;
    #pragma unroll
    for (int off = 16; off > 0; off >>= 1) {
        s  += __shfl_xor_sync(0xffffffffu, s,  off);
        ss += __shfl_xor_sync(0xffffffffu, ss, off);
    }
    __shared__ float rs[8], rss[8];
    if ((t & 31) == 0) { rs[t >> 5] = s; rss[t >> 5] = ss; }
    __syncthreads();
    float sum = 0.f, sumsq = 0.f;
    #pragma unroll
    for (int i = 0; i < 8; i++) { sum += rs[i]; sumsq += rss[i]; }
    float mu  = sum * (1.0f / EMB);
    float var = sumsq * (1.0f / EMB) - mu * mu;
    float inv = rsqrtf(var + 1e-5f);
    float4 gg = ((const float4*)gamma)[t];
    float4 bb = ((const float4*)beta)[t];
    float y0 = (v.x - mu) * inv * gg.x + bb.x;
    float y1 = (v.y - mu) * inv * gg.y + bb.y;
    float y2 = (v.z - mu) * inv * gg.z + bb.z;
    float y3 = (v.w - mu) * inv * gg.w + bb.w;
    size_t base2 = (size_t)row * (EMB / 2) + t * 2;
    ((uint32_t*)o)[base2 + 0] = pack2h(y0, y1);
    ((uint32_t*)o)[base2 + 1] = pack2h(y2, y3);
}

// ================= single-MMA fp16 GEMM, 256x128 tile, BK=64 =================
// C[M,N] = A[M,K] @ B[N,K]^T ; 8 warps (4Mx2N), warp tile 64x64.
#define ROWB      144                    /* 128B data + 16B pad */
#define A_TILE_B  (256 * ROWB)           /* 36864 */
#define B_TILE_B  (128 * ROWB)           /* 18432 */
#define STAGE_B   (A_TILE_B + B_TILE_B)  /* 55296 */
#define GEMM_SMEM (3 * STAGE_B)          /* 165888 */

template <int OM, bool BIAS, bool RELU, bool RES>   // OM: 0=f32 out, 1=fp16 out
__global__ __launch_bounds__(256)
void tc_gemm_kernel(const __half* __restrict__ A, const __half* __restrict__ B,
                    const float* __restrict__ bias, const float* __restrict__ res,
                    float* __restrict__ Cf, __half* __restrict__ Ch,
                    int M, int N, int K) {
    extern __shared__ char smc[];
    const uint32_t smb = smem_u32(smc);
    const int tid  = threadIdx.x;
    const int wid  = tid >> 5;
    const int lane = tid & 31;
    const int wm   = wid & 3;      // 4 m-quarters of 64 rows
    const int wn   = wid >> 2;     // 2 n-halves of 64 cols
    const int bm   = blockIdx.y * 256;
    const int bn   = blockIdx.x * 128;

    const uint32_t a_off = (uint32_t)((wm * 64 + (lane & 15)) * ROWB + (lane >> 4) * 16);
    const uint32_t b_off = (uint32_t)((wn * 64 + ((lane >> 4) & 1) * 8 + (lane & 7)) * ROWB
                                      + ((lane >> 3) & 1) * 16);

    float acc[4][8][4];
    #pragma unroll
    for (int i = 0; i < 4; i++)
        #pragma unroll
        for (int j = 0; j < 8; j++)
            #pragma unroll
            for (int q = 0; q < 4; q++) acc[i][j][q] = 0.f;

    const int S = K >> 6;   // BK = 64

    auto issue = [&](int s, int buf) {
        int k0 = s << 6;
        uint32_t dstb = smb + buf * STAGE_B;
        #pragma unroll
        for (int i = 0; i < 8; i++) {              // A: 256 rows x 8 chunks
            int id = tid + i * 256;
            int r = id >> 3, c = id & 7;
            CP_ASYNC16(dstb + r * ROWB + c * 16,
                       A + (size_t)(bm + r) * K + k0 + c * 8);
        }
        #pragma unroll
        for (int i = 0; i < 4; i++) {              // B: 128 rows x 8 chunks
            int id = tid + i * 256;
            int r = id >> 3, c = id & 7;
            CP_ASYNC16(dstb + A_TILE_B + r * ROWB + c * 16,
                       B + (size_t)(bn + r) * K + k0 + c * 8);
        }
    };

    issue(0, 0); CP_COMMIT();
    if (S > 1) { issue(1, 1); CP_COMMIT(); }

    for (int s = 0; s < S; s++) {
        if (s + 1 < S) { CP_WAIT1(); } else { CP_WAIT0(); }
        __syncthreads();
        if (s + 2 < S) { issue(s + 2, (s + 2) % 3); CP_COMMIT(); }

        const uint32_t stg = smb + (s % 3) * STAGE_B;
        const uint32_t aB = stg + a_off;
        const uint32_t bB = stg + A_TILE_B + b_off;
        #pragma unroll
        for (int ks = 0; ks < 4; ks++) {
            const uint32_t ko = ks * 32;
            uint32_t ahf[4][4];
            #pragma unroll
            for (int mt = 0; mt < 4; mt++)
                ldsm4(ahf[mt], aB + mt * (16 * ROWB) + ko);
            uint32_t bhf[4][4];
            #pragma unroll
            for (int p = 0; p < 4; p++)
                ldsm4(bhf[p], bB + p * (16 * ROWB) + ko);
            #pragma unroll
            for (int mt = 0; mt < 4; mt++) {
                #pragma unroll
                for (int nt = 0; nt < 8; nt++) {
                    const uint32_t* bh = &bhf[nt >> 1][(nt & 1) * 2];
                    mma_f16(acc[mt][nt], ahf[mt], bh);
                }
            }
        }
    }

    const int me = bm + wm * 64 + (lane >> 2);
    const int ne = bn + wn * 64 + (lane & 3) * 2;
    #pragma unroll
    for (int mt = 0; mt < 4; mt++) {
        #pragma unroll
        for (int nt = 0; nt < 8; nt++) {
            #pragma unroll
            for (int half = 0; half < 2; half++) {
                int m = me + mt * 16 + half * 8;
                int n = ne + nt * 8;
                float v0 = acc[mt][nt][half * 2 + 0];
                float v1 = acc[mt][nt][half * 2 + 1];
                if (BIAS) {
                    float2 bb = *(const float2*)(bias + n);
                    v0 += bb.x; v1 += bb.y;
                }
                if (RELU) { v0 = fmaxf(v0, 0.f); v1 = fmaxf(v1, 0.f); }
                if (RES) {
                    float2 rr = *(const float2*)(res + (size_t)m * N + n);
                    v0 += rr.x; v1 += rr.y;
                }
                if (OM == 0) {
                    float2 o; o.x = v0; o.y = v1;
                    *(float2*)(Cf + (size_t)m * N + n) = o;
                } else {
                    *(uint32_t*)(Ch + (size_t)m * N + n) = pack2h(v0, v1);
                }
            }
        }
    }
}

// ================= fp16 flash attention (single-MMA, cp.async K/V) ==========
#define AROWB 144
#define AQ_B  (128 * AROWB)
#define AKV_B (64 * AROWB)
#define OKV(buf) (AQ_B + (buf) * 2 * AKV_B)
#define ATT_SMEM (AQ_B + 4 * AKV_B)
#define NKV (SEQ / 64)

__global__ __launch_bounds__(256, 1)
void attention_tc_kernel(const __half* __restrict__ QKV, __half* __restrict__ O) {
    extern __shared__ char smc[];
    const uint32_t smb = smem_u32(smc);
    const int tid  = threadIdx.x;
    const int wid  = tid >> 5;
    const int lane = tid & 31;
    const int bh = blockIdx.y;
    const int b = bh >> 4, h = bh & 15;
    const int q0 = blockIdx.x * 128;
    const size_t base = ((size_t)b * SEQ) * QKVS + (size_t)h * DH;

    const __half* Kg = QKV + base + 1024;
    const __half* Vg = QKV + base + 2048;

    auto issue_kv = [&](int t, int buf) {
        const __half* Kt = Kg + (size_t)(t * 64) * QKVS;
        const __half* Vt = Vg + (size_t)(t * 64) * QKVS;
        #pragma unroll
        for (int i = 0; i < 2; i++) {
            int id = tid + i * 256;
            int r = id >> 3, c = id & 7;
            uint32_t d = smb + OKV(buf) + r * AROWB + c * 16;
            CP_ASYNC16(d,         Kt + (size_t)r * QKVS + c * 8);
            CP_ASYNC16(d + AKV_B, Vt + (size_t)r * QKVS + c * 8);
        }
    };

    {
        const __half* Qt = QKV + base + (size_t)q0 * QKVS;
        #pragma unroll
        for (int i = 0; i < 4; i++) {
            int id = tid + i * 256;
            int r = id >> 3, c = id & 7;
            CP_ASYNC16(smb + r * AROWB + c * 16, Qt + (size_t)r * QKVS + c * 8);
        }
        issue_kv(0, 0); CP_COMMIT();
        issue_kv(1, 1); CP_COMMIT();
    }
    CP_WAIT1();
    __syncthreads();

    uint32_t qf[4][4];
    {
        uint32_t a_off = (uint32_t)((wid * 16 + (lane & 15)) * AROWB + (lane >> 4) * 16);
        #pragma unroll
        for (int ks = 0; ks < 4; ks++)
            ldsm4(qf[ks], smb + a_off + ks * 32);
    }

    const uint32_t kb_off = (uint32_t)(( ((lane >> 4) & 1) * 8 + (lane & 7) ) * AROWB
                                       + ((lane >> 3) & 1) * 16);
    const uint32_t vb_off = (uint32_t)(( ((lane >> 3) & 1) * 8 + (lane & 7) ) * AROWB
                                       + ((lane >> 4) & 1) * 16);

    float oacc[8][4];
    #pragma unroll
    for (int i = 0; i < 8; i++)
        #pragma unroll
        for (int j = 0; j < 4; j++) oacc[i][j] = 0.f;
    float m0 = -1e30f, m1 = -1e30f, l0 = 0.f, l1 = 0.f;

    for (int t = 0; t < NKV; t++) {
        const int buf = t & 1;
        const uint32_t kB = smb + OKV(buf) + kb_off;
        const uint32_t vB = smb + OKV(buf) + AKV_B + vb_off;

        float s[8][4];
        #pragma unroll
        for (int i = 0; i < 8; i++)
            #pragma unroll
            for (int j = 0; j < 4; j++) s[i][j] = 0.f;
        #pragma unroll
        for (int ks = 0; ks < 4; ks++) {
            uint32_t kb[4][4];
            #pragma unroll
            for (int p = 0; p < 4; p++)
                ldsm4(kb[p], kB + p * (16 * AROWB) + ks * 32);
            #pragma unroll
            for (int p = 0; p < 4; p++) {
                #pragma unroll
                for (int half = 0; half < 2; half++)
                    mma_f16(s[2 * p + half], qf[ks], &kb[p][half * 2]);
            }
        }

        float rmax0 = -1e30f, rmax1 = -1e30f;
        #pragma unroll
        for (int nt = 0; nt < 8; nt++) {
            rmax0 = fmaxf(rmax0, fmaxf(s[nt][0], s[nt][1]));
            rmax1 = fmaxf(rmax1, fmaxf(s[nt][2], s[nt][3]));
        }
        rmax0 = fmaxf(rmax0, __shfl_xor_sync(0xffffffffu, rmax0, 1));
        rmax0 = fmaxf(rmax0, __shfl_xor_sync(0xffffffffu, rmax0, 2));
        rmax1 = fmaxf(rmax1, __shfl_xor_sync(0xffffffffu, rmax1, 1));
        rmax1 = fmaxf(rmax1, __shfl_xor_sync(0xffffffffu, rmax1, 2));
        float mnew0 = fmaxf(m0, rmax0), mnew1 = fmaxf(m1, rmax1);
        float corr0 = ex2(m0 - mnew0),  corr1 = ex2(m1 - mnew1);
        float rs0 = 0.f, rs1 = 0.f;
        #pragma unroll
        for (int nt = 0; nt < 8; nt++) {
            s[nt][0] = ex2(s[nt][0] - mnew0);
            s[nt][1] = ex2(s[nt][1] - mnew0);
            s[nt][2] = ex2(s[nt][2] - mnew1);
            s[nt][3] = ex2(s[nt][3] - mnew1);
            rs0 += s[nt][0] + s[nt][1];
            rs1 += s[nt][2] + s[nt][3];
        }
        rs0 += __shfl_xor_sync(0xffffffffu, rs0, 1);
        rs0 += __shfl_xor_sync(0xffffffffu, rs0, 2);
        rs1 += __shfl_xor_sync(0xffffffffu, rs1, 1);
        rs1 += __shfl_xor_sync(0xffffffffu, rs1, 2);
        l0 = l0 * corr0 + rs0;
        l1 = l1 * corr1 + rs1;
        m0 = mnew0; m1 = mnew1;
        #pragma unroll
        for (int nt = 0; nt < 8; nt++) {
            oacc[nt][0] *= corr0; oacc[nt][1] *= corr0;
            oacc[nt][2] *= corr1; oacc[nt][3] *= corr1;
        }

        #pragma unroll
        for (int ks = 0; ks < 4; ks++) {
            uint32_t pa[4];
            pa[0] = pack2h(s[2 * ks][0],     s[2 * ks][1]);
            pa[1] = pack2h(s[2 * ks][2],     s[2 * ks][3]);
            pa[2] = pack2h(s[2 * ks + 1][0], s[2 * ks + 1][1]);
            pa[3] = pack2h(s[2 * ks + 1][2], s[2 * ks + 1][3]);
            #pragma unroll
            for (int p = 0; p < 4; p++) {
                uint32_t vb[4];
                ldsm4t(vb, vB + ks * (16 * AROWB) + p * 32);
                #pragma unroll
                for (int half = 0; half < 2; half++)
                    mma_f16(oacc[2 * p + half], pa, &vb[half * 2]);
            }
        }
        __syncthreads();

        if (t + 2 < NKV) {
            issue_kv(t + 2, buf); CP_COMMIT();
            CP_WAIT1();
        } else if (t + 1 < NKV) {
            CP_WAIT0();
        }
        __syncthreads();
    }

    float inv0 = 1.f / l0, inv1 = 1.f / l1;
    int qrow = q0 + wid * 16 + (lane >> 2);
    size_t t0 = ((size_t)b * SEQ + qrow) * EMB + h * DH;
    size_t t1 = t0 + (size_t)8 * EMB;
    #pragma unroll
    for (int nt = 0; nt < 8; nt++) {
        int d = nt * 8 + (lane & 3) * 2;
        *(uint32_t*)(O + t0 + d) = pack2h(oacc[nt][0] * inv0, oacc[nt][1] * inv0);
        *(uint32_t*)(O + t1 + d) = pack2h(oacc[nt][2] * inv1, oacc[nt][3] * inv1);
    }
}

// ================= launcher =================
extern "C" void kernel_launch(void* const* d_in, const int* in_sizes, int n_in,
                              void* d_out, int out_size) {
    const float* x    = (const float*)d_in[0];
    const float* Wq   = (const float*)d_in[1];
    const float* Wk   = (const float*)d_in[2];
    const float* Wv   = (const float*)d_in[3];
    const float* Wo   = (const float*)d_in[4];
    const float* bo   = (const float*)d_in[5];
    const float* ln1g = (const float*)d_in[6];
    const float* ln1b = (const float*)d_in[7];
    const float* ln2g = (const float*)d_in[8];
    const float* ln2b = (const float*)d_in[9];
    const float* W1   = (const float*)d_in[10];
    const float* b1   = (const float*)d_in[11];
    const float* W2   = (const float*)d_in[12];
    const float* b2   = (const float*)d_in[13];
    float* out = (float*)d_out;

    __half *xn, *at, *hbuf, *wqkv, *wo, *w1, *w2, *qkvh;
    float *x1;
    cudaGetSymbolAddress((void**)&xn, g_xn);
    cudaGetSymbolAddress((void**)&at, g_at);
    cudaGetSymbolAddress((void**)&hbuf, g_h);
    cudaGetSymbolAddress((void**)&wqkv, g_wqkv);
    cudaGetSymbolAddress((void**)&wo,  g_wo);
    cudaGetSymbolAddress((void**)&w1,  g_w1);
    cudaGetSymbolAddress((void**)&w2,  g_w2);
    cudaGetSymbolAddress((void**)&qkvh, g_qkvh);
    cudaGetSymbolAddress((void**)&x1,  g_x1);

    cudaFuncSetAttribute(tc_gemm_kernel<1, false, false, false>,
                         cudaFuncAttributeMaxDynamicSharedMemorySize, GEMM_SMEM);
    cudaFuncSetAttribute(tc_gemm_kernel<0, true, false, true>,
                         cudaFuncAttributeMaxDynamicSharedMemorySize, GEMM_SMEM);
    cudaFuncSetAttribute(tc_gemm_kernel<1, true, true, false>,
                         cudaFuncAttributeMaxDynamicSharedMemorySize, GEMM_SMEM);
    cudaFuncSetAttribute(attention_tc_kernel,
                         cudaFuncAttributeMaxDynamicSharedMemorySize, ATT_SMEM);

    const float QS = 0.1803368801111204f;  // 0.125 * log2(e)
    const int nE = EMB * EMB / 4, nF = DFF * EMB / 4;

    CvtJobs jobs;
    jobs.src[0] = Wq; jobs.dst[0] = wqkv;                         jobs.n4[0] = nE; jobs.scale[0] = QS;
    jobs.src[1] = Wk; jobs.dst[1] = wqkv + (size_t)EMB * EMB;     jobs.n4[1] = nE; jobs.scale[1] = 1.f;
    jobs.src[2] = Wv; jobs.dst[2] = wqkv + (size_t)2 * EMB * EMB; jobs.n4[2] = nE; jobs.scale[2] = 1.f;
    jobs.src[3] = Wo; jobs.dst[3] = wo; jobs.n4[3] = nE; jobs.scale[3] = 1.f;
    jobs.src[4] = W1; jobs.dst[4] = w1; jobs.n4[4] = nF; jobs.scale[4] = 1.f;
    jobs.src[5] = W2; jobs.dst[5] = w2; jobs.n4[5] = nF; jobs.scale[5] = 1.f;
    cvt_all_kernel<<<dim3(nF / 256, 6), 256>>>(jobs);

    // 1. LN1 -> xn fp16
    layernorm_kernel<<<T_TOK, 256>>>(x, ln1g, ln1b, xn);

    // 2. fused QKV projection -> qkv fp16 (Q pre-scaled via weights)
    dim3 gQKV(QKVS / 128, T_TOK / 256);
    tc_gemm_kernel<1, false, false, false><<<gQKV, 256, GEMM_SMEM>>>(
        xn, wqkv, nullptr, nullptr, nullptr, qkvh, T_TOK, QKVS, EMB);

    // 3. attention -> at fp16
    attention_tc_kernel<<<dim3(SEQ / 128, NBATCH * NH), 256, ATT_SMEM>>>(qkvh, at);

    // 4. O projection + bias + residual(x) -> x1 (f32)
    dim3 gE(EMB / 128, T_TOK / 256);
    tc_gemm_kernel<0, true, false, true><<<gE, 256, GEMM_SMEM>>>(
        at, wo, bo, x, x1, nullptr, T_TOK, EMB, EMB);

    // 5. LN2 -> xn fp16
    layernorm_kernel<<<T_TOK, 256>>>(x1, ln2g, ln2b, xn);

    // 6. FF1 + bias + relu -> h fp16
    dim3 gF(DFF / 128, T_TOK / 256);
    tc_gemm_kernel<1, true, true, false><<<gF, 256, GEMM_SMEM>>>(
        xn, w1, b1, nullptr, nullptr, hbuf, T_TOK, DFF, EMB);

    // 7. FF2 + bias + residual(x1) -> out (f32)
    tc_gemm_kernel<0, true, false, true><<<gE, 256, GEMM_SMEM>>>(
        hbuf, w2, b2, x1, out, nullptr, T_TOK, EMB, DFF);
}

// round 11
// speedup vs baseline: 1.0683x; 1.0683x over previous
#include <cuda_runtime.h>
#include <cuda_bf16.h>
#include <cuda_fp16.h>
#include <math.h>
#include <cstdint>

#define T_TOK 8192
#define EMB   1024
#define DFF   4096
#define NH    16
#define DH    64
#define SEQ   2048
#define NBATCH 4
#define QKVS  3072

// ================= PTX helpers =================
__device__ __forceinline__ uint32_t smem_u32(const void* p) {
    uint32_t a;
    asm("{ .reg .u64 t; cvta.to.shared.u64 t, %1; cvt.u32.u64 %0, t; }" : "=r"(a) : "l"(p));
    return a;
}
#define CP_ASYNC16(dst, src) \
    asm volatile("cp.async.cg.shared.global [%0], [%1], 16;" :: "r"(dst), "l"(src))
#define CP_COMMIT() asm volatile("cp.async.commit_group;" ::: "memory")
#define CP_WAIT1()  asm volatile("cp.async.wait_group 1;" ::: "memory")
#define CP_WAIT0()  asm volatile("cp.async.wait_group 0;" ::: "memory")

__device__ __forceinline__ void ldsm4(uint32_t* r, uint32_t addr) {
    asm volatile("ldmatrix.sync.aligned.m8n8.x4.shared.b16 {%0,%1,%2,%3}, [%4];"
                 : "=r"(r[0]), "=r"(r[1]), "=r"(r[2]), "=r"(r[3]) : "r"(addr));
}
__device__ __forceinline__ void ldsm4t(uint32_t* r, uint32_t addr) {
    asm volatile("ldmatrix.sync.aligned.m8n8.x4.trans.shared.b16 {%0,%1,%2,%3}, [%4];"
                 : "=r"(r[0]), "=r"(r[1]), "=r"(r[2]), "=r"(r[3]) : "r"(addr));
}
__device__ __forceinline__ void mma_f16(float* c, const uint32_t* a, const uint32_t* b) {
    asm volatile(
        "mma.sync.aligned.m16n8k16.row.col.f32.f16.f16.f32 "
        "{%0,%1,%2,%3}, {%4,%5,%6,%7}, {%8,%9}, {%0,%1,%2,%3};"
        : "+f"(c[0]), "+f"(c[1]), "+f"(c[2]), "+f"(c[3])
        : "r"(a[0]), "r"(a[1]), "r"(a[2]), "r"(a[3]), "r"(b[0]), "r"(b[1]));
}
__device__ __forceinline__ float ex2(float x) {
    float y;
    asm("ex2.approx.f32 %0, %1;" : "=f"(y) : "f"(x));
    return y;
}
__device__ __forceinline__ uint32_t pack2h(float a, float b) {
    __half2 h = __floats2half2_rn(a, b);
    return *(uint32_t*)&h;
}

// ================= scratch =================
__device__ __half g_xn[(size_t)T_TOK * EMB];
__device__ __half g_qkvh[(size_t)T_TOK * QKVS];
__device__ float g_x1[(size_t)T_TOK * EMB];
__device__ __half g_at[(size_t)T_TOK * EMB];
__device__ __half g_h [(size_t)T_TOK * DFF];
__device__ __half g_wqkv[(size_t)3 * EMB * EMB];
__device__ __half g_wo[(size_t)EMB * EMB];
__device__ __half g_w1[(size_t)DFF * EMB];
__device__ __half g_w2[(size_t)EMB * DFF];

// ================= fused weight fp32 -> fp16 =================
struct CvtJobs {
    const float* src[6];
    __half*      dst[6];
    int          n4[6];
    float        scale[6];
};
__global__ void cvt_all_kernel(CvtJobs jobs) {
    int j = blockIdx.y;
    int i = blockIdx.x * blockDim.x + threadIdx.x;
    if (i >= jobs.n4[j]) return;
    float sc = jobs.scale[j];
    float4 v = ((const float4*)jobs.src[j])[i];
    ((uint32_t*)jobs.dst[j])[i * 2 + 0] = pack2h(v.x * sc, v.y * sc);
    ((uint32_t*)jobs.dst[j])[i * 2 + 1] = pack2h(v.z * sc, v.w * sc);
}

// ================= LayerNorm -> fp16 =================
__global__ void layernorm_kernel(const float* __restrict__ x,
                                 const float* __restrict__ gamma,
                                 const float* __restrict__ beta,
                                 __half* __restrict__ o) {
    int row = blockIdx.x;
    int t = threadIdx.x;
    const float4* xr = (const float4*)(x + (size_t)row * EMB);
    float4 v = xr[t];
    float s  = v.x + v.y + v.z + v.w;
    float ss = v.x * v.x + v.y * v.y + v.z * v.z + v.w * v.w;
    #pragma unroll
    for (int off = 16; off > 0; off >>= 1) {
        s  += __shfl_xor_sync(0xffffffffu, s,  off);
        ss += __shfl_xor_sync(0xffffffffu, ss, off);
    }
    __shared__ float rs[8], rss[8];
    if ((t & 31) == 0) { rs[t >> 5] = s; rss[t >> 5] = ss; }
    __syncthreads();
    float sum = 0.f, sumsq = 0.f;
    #pragma unroll
    for (int i = 0; i < 8; i++) { sum += rs[i]; sumsq += rss[i]; }
    float mu  = sum * (1.0f / EMB);
    float var = sumsq * (1.0f / EMB) - mu * mu;
    float inv = rsqrtf(var + 1e-5f);
    float4 gg = ((const float4*)gamma)[t];
    float4 bb = ((const float4*)beta)[t];
    float y0 = (v.x - mu) * inv * gg.x + bb.x;
    float y1 = (v.y - mu) * inv * gg.y + bb.y;
    float y2 = (v.z - mu) * inv * gg.z + bb.z;
    float y3 = (v.w - mu) * inv * gg.w + bb.w;
    size_t base2 = (size_t)row * (EMB / 2) + t * 2;
    ((uint32_t*)o)[base2 + 0] = pack2h(y0, y1);
    ((uint32_t*)o)[base2 + 1] = pack2h(y2, y3);
}

// ================= single-MMA fp16 GEMM, BK=64, frag-pipelined ==============
// C[M,N] = A[M,K] @ B[N,K]^T ; 128x128 CTA tile, 8 warps (2Mx4N).
#define ROWB      144                   /* 128B data + 16B pad */
#define TILE_B    (128 * ROWB)          /* 18432 */
#define STAGE_B   (2 * TILE_B)          /* 36864 */
#define GEMM_SMEM (3 * STAGE_B)         /* 110592 */

template <int OM, bool BIAS, bool RELU, bool RES>   // OM: 0=f32 out, 1=fp16 out
__global__ __launch_bounds__(256)
void tc_gemm_kernel(const __half* __restrict__ A, const __half* __restrict__ B,
                    const float* __restrict__ bias, const float* __restrict__ res,
                    float* __restrict__ Cf, __half* __restrict__ Ch,
                    int M, int N, int K) {
    extern __shared__ char smc[];
    const uint32_t smb = smem_u32(smc);
    const int tid  = threadIdx.x;
    const int wid  = tid >> 5;
    const int lane = tid & 31;
    const int wm   = wid & 1;
    const int wn   = wid >> 1;
    const int bm   = blockIdx.y * 128;
    const int bn   = blockIdx.x * 128;

    const uint32_t a_off = (uint32_t)((wm * 64 + (lane & 15)) * ROWB + (lane >> 4) * 16);
    const uint32_t b_off = (uint32_t)((wn * 32 + ((lane >> 4) & 1) * 8 + (lane & 7)) * ROWB
                                      + ((lane >> 3) & 1) * 16);

    float acc[4][4][4];
    #pragma unroll
    for (int i = 0; i < 4; i++)
        #pragma unroll
        for (int j = 0; j < 4; j++)
            #pragma unroll
            for (int q = 0; q < 4; q++) acc[i][j][q] = 0.f;

    const int S = K >> 6;   // BK = 64

    auto issue = [&](int s, int buf) {
        int k0 = s << 6;
        uint32_t dstb = smb + buf * STAGE_B;
        #pragma unroll
        for (int i = 0; i < 4; i++) {
            int id = tid + i * 256;
            int r = id >> 3, c = id & 7;
            uint32_t d = dstb + r * ROWB + c * 16;
            CP_ASYNC16(d,          A + (size_t)(bm + r) * K + k0 + c * 8);
            CP_ASYNC16(d + TILE_B, B + (size_t)(bn + r) * K + k0 + c * 8);
        }
    };

    issue(0, 0); CP_COMMIT();
    if (S > 1) { issue(1, 1); CP_COMMIT(); }

    // double-buffered register fragments: [buf][...]
    uint32_t ahf[2][4][4];
    uint32_t bhf[2][2][4];

    for (int s = 0; s < S; s++) {
        if (s + 1 < S) { CP_WAIT1(); } else { CP_WAIT0(); }
        __syncthreads();
        if (s + 2 < S) { issue(s + 2, (s + 2) % 3); CP_COMMIT(); }

        const uint32_t stg = smb + (s % 3) * STAGE_B;
        const uint32_t aB = stg + a_off;
        const uint32_t bB = stg + TILE_B + b_off;

        // prime ks=0 into buffer 0
        #pragma unroll
        for (int mt = 0; mt < 4; mt++)
            ldsm4(ahf[0][mt], aB + mt * (16 * ROWB));
        #pragma unroll
        for (int p = 0; p < 2; p++)
            ldsm4(bhf[0][p], bB + p * (16 * ROWB));

        #pragma unroll
        for (int ks = 0; ks < 4; ks++) {
            const int cur = ks & 1;
            const int nxt = cur ^ 1;
            // prefetch ks+1 fragments (overlaps the MMAs below)
            if (ks < 3) {
                const uint32_t ko = (ks + 1) * 32;
                #pragma unroll
                for (int mt = 0; mt < 4; mt++)
                    ldsm4(ahf[nxt][mt], aB + mt * (16 * ROWB) + ko);
                #pragma unroll
                for (int p = 0; p < 2; p++)
                    ldsm4(bhf[nxt][p], bB + p * (16 * ROWB) + ko);
            }
            #pragma unroll
            for (int mt = 0; mt < 4; mt++) {
                #pragma unroll
                for (int nt = 0; nt < 4; nt++) {
                    const uint32_t* bh = &bhf[cur][nt >> 1][(nt & 1) * 2];
                    mma_f16(acc[mt][nt], ahf[cur][mt], bh);
                }
            }
        }
    }

    const int me = bm + wm * 64 + (lane >> 2);
    const int ne = bn + wn * 32 + (lane & 3) * 2;
    #pragma unroll
    for (int mt = 0; mt < 4; mt++) {
        #pragma unroll
        for (int nt = 0; nt < 4; nt++) {
            #pragma unroll
            for (int half = 0; half < 2; half++) {
                int m = me + mt * 16 + half * 8;
                int n = ne + nt * 8;
                float v0 = acc[mt][nt][half * 2 + 0];
                float v1 = acc[mt][nt][half * 2 + 1];
                if (BIAS) {
                    float2 bb = *(const float2*)(bias + n);
                    v0 += bb.x; v1 += bb.y;
                }
                if (RELU) { v0 = fmaxf(v0, 0.f); v1 = fmaxf(v1, 0.f); }
                if (RES) {
                    float2 rr = *(const float2*)(res + (size_t)m * N + n);
                    v0 += rr.x; v1 += rr.y;
                }
                if (OM == 0) {
                    float2 o; o.x = v0; o.y = v1;
                    *(float2*)(Cf + (size_t)m * N + n) = o;
                } else {
                    *(uint32_t*)(Ch + (size_t)m * N + n) = pack2h(v0, v1);
                }
            }
        }
    }
}

// ================= fp16 flash attention (single-MMA, cp.async K/V) ==========
#define AROWB 144
#define AQ_B  (128 * AROWB)
#define AKV_B (64 * AROWB)
#define OKV(buf) (AQ_B + (buf) * 2 * AKV_B)
#define ATT_SMEM (AQ_B + 4 * AKV_B)
#define NKV (SEQ / 64)

__global__ __launch_bounds__(256, 1)
void attention_tc_kernel(const __half* __restrict__ QKV, __half* __restrict__ O) {
    extern __shared__ char smc[];
    const uint32_t smb = smem_u32(smc);
    const int tid  = threadIdx.x;
    const int wid  = tid >> 5;
    const int lane = tid & 31;
    const int bh = blockIdx.y;
    const int b = bh >> 4, h = bh & 15;
    const int q0 = blockIdx.x * 128;
    const size_t base = ((size_t)b * SEQ) * QKVS + (size_t)h * DH;

    const __half* Kg = QKV + base + 1024;
    const __half* Vg = QKV + base + 2048;

    auto issue_kv = [&](int t, int buf) {
        const __half* Kt = Kg + (size_t)(t * 64) * QKVS;
        const __half* Vt = Vg + (size_t)(t * 64) * QKVS;
        #pragma unroll
        for (int i = 0; i < 2; i++) {
            int id = tid + i * 256;
            int r = id >> 3, c = id & 7;
            uint32_t d = smb + OKV(buf) + r * AROWB + c * 16;
            CP_ASYNC16(d,         Kt + (size_t)r * QKVS + c * 8);
            CP_ASYNC16(d + AKV_B, Vt + (size_t)r * QKVS + c * 8);
        }
    };

    {
        const __half* Qt = QKV + base + (size_t)q0 * QKVS;
        #pragma unroll
        for (int i = 0; i < 4; i++) {
            int id = tid + i * 256;
            int r = id >> 3, c = id & 7;
            CP_ASYNC16(smb + r * AROWB + c * 16, Qt + (size_t)r * QKVS + c * 8);
        }
        issue_kv(0, 0); CP_COMMIT();
        issue_kv(1, 1); CP_COMMIT();
    }
    CP_WAIT1();
    __syncthreads();

    uint32_t qf[4][4];
    {
        uint32_t a_off = (uint32_t)((wid * 16 + (lane & 15)) * AROWB + (lane >> 4) * 16);
        #pragma unroll
        for (int ks = 0; ks < 4; ks++)
            ldsm4(qf[ks], smb + a_off + ks * 32);
    }

    const uint32_t kb_off = (uint32_t)(( ((lane >> 4) & 1) * 8 + (lane & 7) ) * AROWB
                                       + ((lane >> 3) & 1) * 16);
    const uint32_t vb_off = (uint32_t)(( ((lane >> 3) & 1) * 8 + (lane & 7) ) * AROWB
                                       + ((lane >> 4) & 1) * 16);

    float oacc[8][4];
    #pragma unroll
    for (int i = 0; i < 8; i++)
        #pragma unroll
        for (int j = 0; j < 4; j++) oacc[i][j] = 0.f;
    float m0 = -1e30f, m1 = -1e30f, l0 = 0.f, l1 = 0.f;

    for (int t = 0; t < NKV; t++) {
        const int buf = t & 1;
        const uint32_t kB = smb + OKV(buf) + kb_off;
        const uint32_t vB = smb + OKV(buf) + AKV_B + vb_off;

        float s[8][4];
        #pragma unroll
        for (int i = 0; i < 8; i++)
            #pragma unroll
            for (int j = 0; j < 4; j++) s[i][j] = 0.f;
        #pragma unroll
        for (int ks = 0; ks < 4; ks++) {
            uint32_t kb[4][4];
            #pragma unroll
            for (int p = 0; p < 4; p++)
                ldsm4(kb[p], kB + p * (16 * AROWB) + ks * 32);
            #pragma unroll
            for (int p = 0; p < 4; p++) {
                #pragma unroll
                for (int half = 0; half < 2; half++)
                    mma_f16(s[2 * p + half], qf[ks], &kb[p][half * 2]);
            }
        }

        float rmax0 = -1e30f, rmax1 = -1e30f;
        #pragma unroll
        for (int nt = 0; nt < 8; nt++) {
            rmax0 = fmaxf(rmax0, fmaxf(s[nt][0], s[nt][1]));
            rmax1 = fmaxf(rmax1, fmaxf(s[nt][2], s[nt][3]));
        }
        rmax0 = fmaxf(rmax0, __shfl_xor_sync(0xffffffffu, rmax0, 1));
        rmax0 = fmaxf(rmax0, __shfl_xor_sync(0xffffffffu, rmax0, 2));
        rmax1 = fmaxf(rmax1, __shfl_xor_sync(0xffffffffu, rmax1, 1));
        rmax1 = fmaxf(rmax1, __shfl_xor_sync(0xffffffffu, rmax1, 2));
        float mnew0 = fmaxf(m0, rmax0), mnew1 = fmaxf(m1, rmax1);
        float corr0 = ex2(m0 - mnew0),  corr1 = ex2(m1 - mnew1);
        float rs0 = 0.f, rs1 = 0.f;
        #pragma unroll
        for (int nt = 0; nt < 8; nt++) {
            s[nt][0] = ex2(s[nt][0] - mnew0);
            s[nt][1] = ex2(s[nt][1] - mnew0);
            s[nt][2] = ex2(s[nt][2] - mnew1);
            s[nt][3] = ex2(s[nt][3] - mnew1);
            rs0 += s[nt][0] + s[nt][1];
            rs1 += s[nt][2] + s[nt][3];
        }
        rs0 += __shfl_xor_sync(0xffffffffu, rs0, 1);
        rs0 += __shfl_xor_sync(0xffffffffu, rs0, 2);
        rs1 += __shfl_xor_sync(0xffffffffu, rs1, 1);
        rs1 += __shfl_xor_sync(0xffffffffu, rs1, 2);
        l0 = l0 * corr0 + rs0;
        l1 = l1 * corr1 + rs1;
        m0 = mnew0; m1 = mnew1;
        #pragma unroll
        for (int nt = 0; nt < 8; nt++) {
            oacc[nt][0] *= corr0; oacc[nt][1] *= corr0;
            oacc[nt][2] *= corr1; oacc[nt][3] *= corr1;
        }

        #pragma unroll
        for (int ks = 0; ks < 4; ks++) {
            uint32_t pa[4];
            pa[0] = pack2h(s[2 * ks][0],     s[2 * ks][1]);
            pa[1] = pack2h(s[2 * ks][2],     s[2 * ks][3]);
            pa[2] = pack2h(s[2 * ks + 1][0], s[2 * ks + 1][1]);
            pa[3] = pack2h(s[2 * ks + 1][2], s[2 * ks + 1][3]);
            #pragma unroll
            for (int p = 0; p < 4; p++) {
                uint32_t vb[4];
                ldsm4t(vb, vB + ks * (16 * AROWB) + p * 32);
                #pragma unroll
                for (int half = 0; half < 2; half++)
                    mma_f16(oacc[2 * p + half], pa, &vb[half * 2]);
            }
        }
        __syncthreads();

        if (t + 2 < NKV) {
            issue_kv(t + 2, buf); CP_COMMIT();
            CP_WAIT1();
        } else if (t + 1 < NKV) {
            CP_WAIT0();
        }
        __syncthreads();
    }

    float inv0 = 1.f / l0, inv1 = 1.f / l1;
    int qrow = q0 + wid * 16 + (lane >> 2);
    size_t t0 = ((size_t)b * SEQ + qrow) * EMB + h * DH;
    size_t t1 = t0 + (size_t)8 * EMB;
    #pragma unroll
    for (int nt = 0; nt < 8; nt++) {
        int d = nt * 8 + (lane & 3) * 2;
        *(uint32_t*)(O + t0 + d) = pack2h(oacc[nt][0] * inv0, oacc[nt][1] * inv0);
        *(uint32_t*)(O + t1 + d) = pack2h(oacc[nt][2] * inv1, oacc[nt][3] * inv1);
    }
}

// ================= launcher =================
extern "C" void kernel_launch(void* const* d_in, const int* in_sizes, int n_in,
                              void* d_out, int out_size) {
    const float* x    = (const float*)d_in[0];
    const float* Wq   = (const float*)d_in[1];
    const float* Wk   = (const float*)d_in[2];
    const float* Wv   = (const float*)d_in[3];
    const float* Wo   = (const float*)d_in[4];
    const float* bo   = (const float*)d_in[5];
    const float* ln1g = (const float*)d_in[6];
    const float* ln1b = (const float*)d_in[7];
    const float* ln2g = (const float*)d_in[8];
    const float* ln2b = (const float*)d_in[9];
    const float* W1   = (const float*)d_in[10];
    const float* b1   = (const float*)d_in[11];
    const float* W2   = (const float*)d_in[12];
    const float* b2   = (const float*)d_in[13];
    float* out = (float*)d_out;

    __half *xn, *at, *hbuf, *wqkv, *wo, *w1, *w2, *qkvh;
    float *x1;
    cudaGetSymbolAddress((void**)&xn, g_xn);
    cudaGetSymbolAddress((void**)&at, g_at);
    cudaGetSymbolAddress((void**)&hbuf, g_h);
    cudaGetSymbolAddress((void**)&wqkv, g_wqkv);
    cudaGetSymbolAddress((void**)&wo,  g_wo);
    cudaGetSymbolAddress((void**)&w1,  g_w1);
    cudaGetSymbolAddress((void**)&w2,  g_w2);
    cudaGetSymbolAddress((void**)&qkvh, g_qkvh);
    cudaGetSymbolAddress((void**)&x1,  g_x1);

    cudaFuncSetAttribute(tc_gemm_kernel<1, false, false, false>,
                         cudaFuncAttributeMaxDynamicSharedMemorySize, GEMM_SMEM);
    cudaFuncSetAttribute(tc_gemm_kernel<0, true, false, true>,
                         cudaFuncAttributeMaxDynamicSharedMemorySize, GEMM_SMEM);
    cudaFuncSetAttribute(tc_gemm_kernel<1, true, true, false>,
                         cudaFuncAttributeMaxDynamicSharedMemorySize, GEMM_SMEM);
    cudaFuncSetAttribute(attention_tc_kernel,
                         cudaFuncAttributeMaxDynamicSharedMemorySize, ATT_SMEM);

    const float QS = 0.1803368801111204f;  // 0.125 * log2(e)
    const int nE = EMB * EMB / 4, nF = DFF * EMB / 4;

    CvtJobs jobs;
    jobs.src[0] = Wq; jobs.dst[0] = wqkv;                         jobs.n4[0] = nE; jobs.scale[0] = QS;
    jobs.src[1] = Wk; jobs.dst[1] = wqkv + (size_t)EMB * EMB;     jobs.n4[1] = nE; jobs.scale[1] = 1.f;
    jobs.src[2] = Wv; jobs.dst[2] = wqkv + (size_t)2 * EMB * EMB; jobs.n4[2] = nE; jobs.scale[2] = 1.f;
    jobs.src[3] = Wo; jobs.dst[3] = wo; jobs.n4[3] = nE; jobs.scale[3] = 1.f;
    jobs.src[4] = W1; jobs.dst[4] = w1; jobs.n4[4] = nF; jobs.scale[4] = 1.f;
    jobs.src[5] = W2; jobs.dst[5] = w2; jobs.n4[5] = nF; jobs.scale[5] = 1.f;
    cvt_all_kernel<<<dim3(nF / 256, 6), 256>>>(jobs);

    // 1. LN1 -> xn fp16
    layernorm_kernel<<<T_TOK, 256>>>(x, ln1g, ln1b, xn);

    // 2. fused QKV projection -> qkv fp16 (Q pre-scaled via weights)
    dim3 gQKV(QKVS / 128, T_TOK / 128);
    tc_gemm_kernel<1, false, false, false><<<gQKV, 256, GEMM_SMEM>>>(
        xn, wqkv, nullptr, nullptr, nullptr, qkvh, T_TOK, QKVS, EMB);

    // 3. attention -> at fp16
    attention_tc_kernel<<<dim3(SEQ / 128, NBATCH * NH), 256, ATT_SMEM>>>(qkvh, at);

    // 4. O projection + bias + residual(x) -> x1 (f32)
    dim3 gE(EMB / 128, T_TOK / 128);
    tc_gemm_kernel<0, true, false, true><<<gE, 256, GEMM_SMEM>>>(
        at, wo, bo, x, x1, nullptr, T_TOK, EMB, EMB);

    // 5. LN2 -> xn fp16
    layernorm_kernel<<<T_TOK, 256>>>(x1, ln2g, ln2b, xn);

    // 6. FF1 + bias + relu -> h fp16
    dim3 gF(DFF / 128, T_TOK / 128);
    tc_gemm_kernel<1, true, true, false><<<gF, 256, GEMM_SMEM>>>(
        xn, w1, b1, nullptr, nullptr, hbuf, T_TOK, DFF, EMB);

    // 7. FF2 + bias + residual(x1) -> out (f32)
    tc_gemm_kernel<0, true, false, true><<<gE, 256, GEMM_SMEM>>>(
        hbuf, w2, b2, x1, out, nullptr, T_TOK, EMB, DFF);
}